// round 4
// baseline (speedup 1.0000x reference)
#include <cuda_runtime.h>
#include <cstdint>

#define NN 100000
#define EE 1600000
#define SCAN_BLOCKS 391   // ceil(NN/256)

// Scratch (static device globals — no allocation in kernel_launch)
__device__ float g_x[(size_t)NN * 128];    // tf32-rounded in_feat
__device__ float g_s[(size_t)NN * 128];    // neigh buffer (tf32-rounded)
__device__ float g_h1[(size_t)NN * 128];   // layer-1 output (tf32-rounded)
__device__ float g_wcat[2][128 * 256];     // tf32 [Ws | Wn] per layer, row-major
__device__ int   g_cnt[NN];
__device__ int   g_excl[NN];
__device__ int   g_blocksum[512];
__device__ int   g_rowstart[NN + 1];
__device__ int   g_cursor[NN];
__device__ int2  g_elist[EE];              // {src, weight_bits} grouped by dst

// ---------------------------------------------------------------------------
// tf32 helpers
// ---------------------------------------------------------------------------
__device__ __forceinline__ float f2tf32(float x) {
    unsigned r;
    asm("cvt.rna.tf32.f32 %0, %1;" : "=r"(r) : "f"(x));
    return __uint_as_float(r);
}

__device__ __forceinline__ void mma_tf32(float c[4],
                                         const unsigned a[4],
                                         const unsigned b[2]) {
    asm volatile(
        "mma.sync.aligned.m16n8k8.row.col.f32.tf32.tf32.f32 "
        "{%0,%1,%2,%3}, {%4,%5,%6,%7}, {%8,%9}, {%0,%1,%2,%3};"
        : "+f"(c[0]), "+f"(c[1]), "+f"(c[2]), "+f"(c[3])
        : "r"(a[0]), "r"(a[1]), "r"(a[2]), "r"(a[3]),
          "r"(b[0]), "r"(b[1]));
}

__device__ __forceinline__ void cp16(float* sdst, const float* gsrc, bool pred) {
    unsigned s = (unsigned)__cvta_generic_to_shared(sdst);
    int sz = pred ? 16 : 0;
    asm volatile("cp.async.cg.shared.global [%0], [%1], 16, %2;"
                 :: "r"(s), "l"(gsrc), "r"(sz));
}
__device__ __forceinline__ void cp_commit() {
    asm volatile("cp.async.commit_group;");
}
__device__ __forceinline__ void cp_wait0() {
    asm volatile("cp.async.wait_group 0;");
}

// ---------------------------------------------------------------------------
// One-time conversions
// ---------------------------------------------------------------------------
__global__ void k_cvtx(const float* __restrict__ x) {
    int i = blockIdx.x * blockDim.x + threadIdx.x;
    if (i >= NN * 32) return;
    float4 v = reinterpret_cast<const float4*>(x)[i];
    v.x = f2tf32(v.x); v.y = f2tf32(v.y);
    v.z = f2tf32(v.z); v.w = f2tf32(v.w);
    reinterpret_cast<float4*>(g_x)[i] = v;
}

__global__ void k_cvtw(const float* __restrict__ Ws1, const float* __restrict__ Wn1,
                       const float* __restrict__ Ws2, const float* __restrict__ Wn2) {
    int i = blockIdx.x * blockDim.x + threadIdx.x;   // 0..65535
    if (i >= 65536) return;
    int l   = i >> 15;
    int rem = i & 32767;     // f*256 + k
    int f   = rem >> 8;
    int k   = rem & 255;
    const float* W = l ? (k < 128 ? Ws2 : Wn2) : (k < 128 ? Ws1 : Wn1);
    g_wcat[l][rem] = f2tf32(W[f * 128 + (k & 127)]);
}

// ---------------------------------------------------------------------------
// CSR build: histogram -> scan -> fill
// ---------------------------------------------------------------------------
__global__ void k_hist(const int* __restrict__ dst) {
    int e = blockIdx.x * blockDim.x + threadIdx.x;
    if (e < EE) atomicAdd(&g_cnt[dst[e]], 1);
}

__global__ void k_scanA() {
    __shared__ int sm[256];
    int i = blockIdx.x * 256 + threadIdx.x;
    int v = (i < NN) ? g_cnt[i] : 0;
    sm[threadIdx.x] = v;
    __syncthreads();
#pragma unroll
    for (int ofs = 1; ofs < 256; ofs <<= 1) {
        int t = (threadIdx.x >= ofs) ? sm[threadIdx.x - ofs] : 0;
        __syncthreads();
        sm[threadIdx.x] += t;
        __syncthreads();
    }
    if (i < NN) g_excl[i] = sm[threadIdx.x] - v;
    if (threadIdx.x == 255) g_blocksum[blockIdx.x] = sm[255];
}

__global__ void k_scanB() {
    __shared__ int sm[512];
    int v = (threadIdx.x < SCAN_BLOCKS) ? g_blocksum[threadIdx.x] : 0;
    sm[threadIdx.x] = v;
    __syncthreads();
#pragma unroll
    for (int ofs = 1; ofs < 512; ofs <<= 1) {
        int t = (threadIdx.x >= ofs) ? sm[threadIdx.x - ofs] : 0;
        __syncthreads();
        sm[threadIdx.x] += t;
        __syncthreads();
    }
    if (threadIdx.x < SCAN_BLOCKS) g_blocksum[threadIdx.x] = sm[threadIdx.x] - v;
}

__global__ void k_scanC() {
    int i = blockIdx.x * 256 + threadIdx.x;
    if (i < NN) {
        int rs = g_excl[i] + g_blocksum[blockIdx.x];
        g_rowstart[i] = rs;
        g_cursor[i] = rs;
    }
    if (i == 0) g_rowstart[NN] = EE;
}

__global__ void k_fill(const int* __restrict__ src,
                       const int* __restrict__ dst,
                       const float* __restrict__ w) {
    int e = blockIdx.x * blockDim.x + threadIdx.x;
    if (e >= EE) return;
    int pos = atomicAdd(&g_cursor[dst[e]], 1);
    g_elist[pos] = make_int2(src[e], __float_as_int(w[e]));
}

// ---------------------------------------------------------------------------
// Gather-aggregate (one warp per node, 4-deep unroll), tf32-rounded output
// ---------------------------------------------------------------------------
__global__ void k_gather(const float* __restrict__ h,
                         float* __restrict__ neigh) {
    const int n = (blockIdx.x * blockDim.x + threadIdx.x) >> 5;
    if (n >= NN) return;
    const int lane = threadIdx.x & 31;

    const int start = g_rowstart[n];
    const int end   = g_rowstart[n + 1];
    const float4* h4 = reinterpret_cast<const float4*>(h);

    float4 acc0 = make_float4(0.f, 0.f, 0.f, 0.f);
    float4 acc1 = make_float4(0.f, 0.f, 0.f, 0.f);

    int i = start;
    for (; i + 3 < end; i += 4) {
        int2 e0 = g_elist[i];
        int2 e1 = g_elist[i + 1];
        int2 e2 = g_elist[i + 2];
        int2 e3 = g_elist[i + 3];
        float4 v0 = h4[(size_t)e0.x * 32 + lane];
        float4 v1 = h4[(size_t)e1.x * 32 + lane];
        float4 v2 = h4[(size_t)e2.x * 32 + lane];
        float4 v3 = h4[(size_t)e3.x * 32 + lane];
        float w0 = __int_as_float(e0.y), w1 = __int_as_float(e1.y);
        float w2 = __int_as_float(e2.y), w3 = __int_as_float(e3.y);
        acc0.x = fmaf(w0, v0.x, acc0.x); acc0.y = fmaf(w0, v0.y, acc0.y);
        acc0.z = fmaf(w0, v0.z, acc0.z); acc0.w = fmaf(w0, v0.w, acc0.w);
        acc1.x = fmaf(w1, v1.x, acc1.x); acc1.y = fmaf(w1, v1.y, acc1.y);
        acc1.z = fmaf(w1, v1.z, acc1.z); acc1.w = fmaf(w1, v1.w, acc1.w);
        acc0.x = fmaf(w2, v2.x, acc0.x); acc0.y = fmaf(w2, v2.y, acc0.y);
        acc0.z = fmaf(w2, v2.z, acc0.z); acc0.w = fmaf(w2, v2.w, acc0.w);
        acc1.x = fmaf(w3, v3.x, acc1.x); acc1.y = fmaf(w3, v3.y, acc1.y);
        acc1.z = fmaf(w3, v3.z, acc1.z); acc1.w = fmaf(w3, v3.w, acc1.w);
    }
    for (; i < end; i++) {
        int2 e0 = g_elist[i];
        float w0 = __int_as_float(e0.y);
        float4 v0 = h4[(size_t)e0.x * 32 + lane];
        acc0.x = fmaf(w0, v0.x, acc0.x); acc0.y = fmaf(w0, v0.y, acc0.y);
        acc0.z = fmaf(w0, v0.z, acc0.z); acc0.w = fmaf(w0, v0.w, acc0.w);
    }

    int deg = end - start;
    float inv = 1.0f / (float)max(deg, 1);
    float4 r;
    r.x = f2tf32((acc0.x + acc1.x) * inv);
    r.y = f2tf32((acc0.y + acc1.y) * inv);
    r.z = f2tf32((acc0.z + acc1.z) * inv);
    r.w = f2tf32((acc0.w + acc1.w) * inv);
    reinterpret_cast<float4*>(neigh)[(size_t)n * 32 + lane] = r;
}

// ---------------------------------------------------------------------------
// Fused SAGE GEMM, tf32 tensor cores, cp.async double-buffered A,
// register-prefetched B. All inputs pre-rounded to tf32.
// Swizzled smem: addr = r*32 + (k ^ ((r&7)<<2))  — conflict-free for both
// STS.128 staging and the mma fragment LDS.32 pattern.
// ---------------------------------------------------------------------------
#define SWZ(r, k) (((r) << 5) + ((k) ^ (((r) & 7) << 2)))

template <bool RELU, bool ROUND_OUT>
__global__ void __launch_bounds__(256, 1)
k_gemm_tf32(const float* __restrict__ X,
            const float* __restrict__ S,
            const float* __restrict__ Wcat,   // [128][256] tf32
            const float* __restrict__ bias,
            float* __restrict__ out) {
    __shared__ float As[2][128 * 32];
    __shared__ float Bs[128 * 32];

    const int tid  = threadIdx.x;
    const int bm0  = blockIdx.x * 128;
    const int wid  = tid >> 5;
    const int lane = tid & 31;
    const int wm   = (wid & 1) * 64;
    const int wn   = (wid >> 1) * 32;
    const int gr   = lane >> 2;
    const int gc   = lane & 3;

    // per-thread staging coords: idx = l*256+tid -> r = idx>>3, c4 = idx&7
    int rr[4], cc4[4];
#pragma unroll
    for (int l = 0; l < 4; l++) {
        int idx = l * 256 + tid;
        rr[l]  = idx >> 3;
        cc4[l] = idx & 7;
    }

    const float4* wcat4 = reinterpret_cast<const float4*>(Wcat);

    float acc[4][4][4];
#pragma unroll
    for (int mi = 0; mi < 4; mi++)
#pragma unroll
        for (int ni = 0; ni < 4; ni++)
#pragma unroll
            for (int c = 0; c < 4; c++) acc[mi][ni][c] = 0.f;

    // --- A-tile cp.async issue for k-tile kt into buffer buf
    auto issueA = [&](int kt, int buf) {
        const float* base = (kt < 4) ? X : S;
        const int kb = (kt & 3) * 32;
#pragma unroll
        for (int l = 0; l < 4; l++) {
            int grow = bm0 + rr[l];
            bool p = grow < NN;
            int gsafe = p ? grow : 0;
            const float* gp = base + (size_t)gsafe * 128 + kb + cc4[l] * 4;
            cp16(&As[buf][SWZ(rr[l], cc4[l] * 4)], gp, p);
        }
        cp_commit();
    };

    // --- B-tile register prefetch for k-tile kt
    float4 breg[4];
    auto loadB = [&](int kt) {
#pragma unroll
        for (int l = 0; l < 4; l++)
            breg[l] = wcat4[(size_t)rr[l] * 64 + kt * 8 + cc4[l]];
    };

    issueA(0, 0);
    loadB(0);

#pragma unroll 1
    for (int kt = 0; kt < 8; kt++) {
        float4 bcur[4];
#pragma unroll
        for (int l = 0; l < 4; l++) bcur[l] = breg[l];
        if (kt < 7) loadB(kt + 1);          // overlap with wait

        cp_wait0();
        __syncthreads();                     // A[kt] visible; Bs free

#pragma unroll
        for (int l = 0; l < 4; l++)
            *reinterpret_cast<float4*>(&Bs[SWZ(rr[l], cc4[l] * 4)]) = bcur[l];

        if (kt < 7) issueA(kt + 1, (kt + 1) & 1);

        __syncthreads();                     // Bs visible

        const float* Ab = As[kt & 1];
#pragma unroll
        for (int ks = 0; ks < 4; ks++) {
            const int k0 = ks * 8;

            unsigned a[4][4];
#pragma unroll
            for (int mi = 0; mi < 4; mi++) {
                int r = wm + mi * 16 + gr;
                a[mi][0] = __float_as_uint(Ab[SWZ(r,     k0 + gc)]);
                a[mi][1] = __float_as_uint(Ab[SWZ(r + 8, k0 + gc)]);
                a[mi][2] = __float_as_uint(Ab[SWZ(r,     k0 + gc + 4)]);
                a[mi][3] = __float_as_uint(Ab[SWZ(r + 8, k0 + gc + 4)]);
            }

            unsigned b[4][2];
#pragma unroll
            for (int ni = 0; ni < 4; ni++) {
                int n = wn + ni * 8 + gr;
                b[ni][0] = __float_as_uint(Bs[SWZ(n, k0 + gc)]);
                b[ni][1] = __float_as_uint(Bs[SWZ(n, k0 + gc + 4)]);
            }

#pragma unroll
            for (int mi = 0; mi < 4; mi++)
#pragma unroll
                for (int ni = 0; ni < 4; ni++)
                    mma_tf32(acc[mi][ni], a[mi], b[ni]);
        }

        __syncthreads();                     // protect As[kt&1] before reuse
    }

    // --- epilogue
#pragma unroll
    for (int ni = 0; ni < 4; ni++) {
        int col = wn + ni * 8 + gc * 2;
        float b0 = bias[col];
        float b1 = bias[col + 1];
#pragma unroll
        for (int mi = 0; mi < 4; mi++) {
            int r0 = bm0 + wm + mi * 16 + gr;
            float2 v0, v1;
            v0.x = acc[mi][ni][0] + b0;
            v0.y = acc[mi][ni][1] + b1;
            v1.x = acc[mi][ni][2] + b0;
            v1.y = acc[mi][ni][3] + b1;
            if (RELU) {
                v0.x = fmaxf(v0.x, 0.f); v0.y = fmaxf(v0.y, 0.f);
                v1.x = fmaxf(v1.x, 0.f); v1.y = fmaxf(v1.y, 0.f);
            }
            if (ROUND_OUT) {
                v0.x = f2tf32(v0.x); v0.y = f2tf32(v0.y);
                v1.x = f2tf32(v1.x); v1.y = f2tf32(v1.y);
            }
            if (r0 < NN)
                *reinterpret_cast<float2*>(&out[(size_t)r0 * 128 + col]) = v0;
            if (r0 + 8 < NN)
                *reinterpret_cast<float2*>(&out[(size_t)(r0 + 8) * 128 + col]) = v1;
        }
    }
}

// ---------------------------------------------------------------------------
// launch
// ---------------------------------------------------------------------------
extern "C" void kernel_launch(void* const* d_in, const int* in_sizes, int n_in,
                              void* d_out, int out_size) {
    const float* in_feat = (const float*)d_in[0];
    const float* weights = (const float*)d_in[1];
    const int*   src     = (const int*)d_in[2];
    const int*   dst     = (const int*)d_in[3];
    const float* Ws1     = (const float*)d_in[4];
    const float* b1      = (const float*)d_in[5];
    const float* Wn1     = (const float*)d_in[6];
    const float* Ws2     = (const float*)d_in[7];
    const float* b2      = (const float*)d_in[8];
    const float* Wn2     = (const float*)d_in[9];
    float* out = (float*)d_out;

    void *p_x, *p_s, *p_h1, *p_cnt, *p_w;
    cudaGetSymbolAddress(&p_x, g_x);
    cudaGetSymbolAddress(&p_s, g_s);
    cudaGetSymbolAddress(&p_h1, g_h1);
    cudaGetSymbolAddress(&p_cnt, g_cnt);
    cudaGetSymbolAddress(&p_w, g_wcat);
    float* x  = (float*)p_x;
    float* s  = (float*)p_s;
    float* h1 = (float*)p_h1;
    float* w0 = (float*)p_w;                 // layer-1 concat weights
    float* w1 = w0 + 128 * 256;              // layer-2 concat weights

    const int eb = (EE + 255) / 256;
    const int gather_blocks = (NN * 32 + 255) / 256;
    const int gemm_blocks = (NN + 127) / 128;

    // --- one-time conversions + CSR build
    k_cvtx<<<(NN * 32 + 255) / 256, 256>>>(in_feat);
    k_cvtw<<<256, 256>>>(Ws1, Wn1, Ws2, Wn2);
    cudaMemsetAsync(p_cnt, 0, NN * sizeof(int), 0);
    k_hist<<<eb, 256>>>(dst);
    k_scanA<<<SCAN_BLOCKS, 256>>>();
    k_scanB<<<1, 512>>>();
    k_scanC<<<SCAN_BLOCKS, 256>>>();
    k_fill<<<eb, 256>>>(src, dst, weights);

    // --- Layer 1
    k_gather<<<gather_blocks, 256>>>(x, s);
    k_gemm_tf32<true, true><<<gemm_blocks, 256>>>(x, s, w0, b1, h1);

    // --- Layer 2
    k_gather<<<gather_blocks, 256>>>(h1, s);
    k_gemm_tf32<false, false><<<gemm_blocks, 256>>>(h1, s, w1, b2, out);
}

// round 5
// speedup vs baseline: 1.0720x; 1.0720x over previous
#include <cuda_runtime.h>
#include <cstdint>

#define NN 100000
#define EE 1600000
#define SCAN_BLOCKS 391   // ceil(NN/256)

// Scratch (static device globals — no allocation in kernel_launch)
__device__ float g_s[(size_t)NN * 128];    // neigh buffer (tf32-rounded)
__device__ float g_h1[(size_t)NN * 128];   // layer-1 output
__device__ float g_wcat[2][128 * 256];     // tf32 [Ws | Wn] per layer, row-major
__device__ int   g_cnt[NN];
__device__ unsigned long long g_state[SCAN_BLOCKS];  // lookback scan state
__device__ int   g_rowstart[NN + 1];
__device__ int   g_cursor[NN];
__device__ int2  g_elist[EE];              // {src, weight_bits} grouped by dst

// ---------------------------------------------------------------------------
// tf32 helpers
// ---------------------------------------------------------------------------
__device__ __forceinline__ float f2tf32(float x) {
    unsigned r;
    asm("cvt.rna.tf32.f32 %0, %1;" : "=r"(r) : "f"(x));
    return __uint_as_float(r);
}

__device__ __forceinline__ void mma_tf32(float c[4],
                                         const unsigned a[4],
                                         const unsigned b[2]) {
    asm volatile(
        "mma.sync.aligned.m16n8k8.row.col.f32.tf32.tf32.f32 "
        "{%0,%1,%2,%3}, {%4,%5,%6,%7}, {%8,%9}, {%0,%1,%2,%3};"
        : "+f"(c[0]), "+f"(c[1]), "+f"(c[2]), "+f"(c[3])
        : "r"(a[0]), "r"(a[1]), "r"(a[2]), "r"(a[3]),
          "r"(b[0]), "r"(b[1]));
}

__device__ __forceinline__ void cp16(float* sdst, const float* gsrc, bool pred) {
    unsigned s = (unsigned)__cvta_generic_to_shared(sdst);
    int sz = pred ? 16 : 0;
    asm volatile("cp.async.cg.shared.global [%0], [%1], 16, %2;"
                 :: "r"(s), "l"(gsrc), "r"(sz));
}
__device__ __forceinline__ void cp_commit() {
    asm volatile("cp.async.commit_group;");
}
__device__ __forceinline__ void cp_wait0() {
    asm volatile("cp.async.wait_group 0;");
}

// ---------------------------------------------------------------------------
// Weight concat + tf32 round (256 KB total — negligible)
// ---------------------------------------------------------------------------
__global__ void k_cvtw(const float* __restrict__ Ws1, const float* __restrict__ Wn1,
                       const float* __restrict__ Ws2, const float* __restrict__ Wn2) {
    int i = blockIdx.x * blockDim.x + threadIdx.x;   // 0..65535
    if (i >= 65536) return;
    int l   = i >> 15;
    int rem = i & 32767;     // f*256 + k
    int f   = rem >> 8;
    int k   = rem & 255;
    const float* W = l ? (k < 128 ? Ws2 : Wn2) : (k < 128 ? Ws1 : Wn1);
    g_wcat[l][rem] = f2tf32(W[f * 128 + (k & 127)]);
}

// ---------------------------------------------------------------------------
// CSR build: histogram -> single-kernel decoupled-lookback scan -> fill
// ---------------------------------------------------------------------------
__global__ void k_hist(const int* __restrict__ dst) {
    int e = blockIdx.x * blockDim.x + threadIdx.x;
    if (e < EE) atomicAdd(&g_cnt[dst[e]], 1);
}

__global__ void k_scan() {
    __shared__ int sm[256];
    __shared__ int s_prefix;
    const int b = blockIdx.x;
    const int t = threadIdx.x;
    const int i = b * 256 + t;

    int v = (i < NN) ? g_cnt[i] : 0;
    sm[t] = v;
    __syncthreads();
#pragma unroll
    for (int ofs = 1; ofs < 256; ofs <<= 1) {
        int tv = (t >= ofs) ? sm[t - ofs] : 0;
        __syncthreads();
        sm[t] += tv;
        __syncthreads();
    }
    int incl  = sm[t];
    int total = sm[255];

    if (t == 0) {
        if (b == 0) {
            atomicExch(&g_state[0], (2ULL << 32) | (unsigned)total);
            s_prefix = 0;
        } else {
            atomicExch(&g_state[b], (1ULL << 32) | (unsigned)total);
            int run = 0;
            for (int p = b - 1; p >= 0; p--) {
                unsigned long long s;
                do { s = atomicAdd(&g_state[p], 0ULL); } while ((s >> 32) == 0ULL);
                run += (int)(unsigned)s;
                if ((s >> 32) == 2ULL) break;
            }
            s_prefix = run;
            atomicExch(&g_state[b], (2ULL << 32) | (unsigned)(run + total));
        }
    }
    __syncthreads();

    if (i < NN) {
        int rs = s_prefix + incl - v;
        g_rowstart[i] = rs;
        g_cursor[i]   = rs;
    }
    if (i == 0) g_rowstart[NN] = EE;
}

__global__ void k_fill(const int* __restrict__ src,
                       const int* __restrict__ dst,
                       const float* __restrict__ w) {
    int e = blockIdx.x * blockDim.x + threadIdx.x;
    if (e >= EE) return;
    int pos = atomicAdd(&g_cursor[dst[e]], 1);
    g_elist[pos] = make_int2(src[e], __float_as_int(w[e]));
}

// ---------------------------------------------------------------------------
// Gather-aggregate: one warp per dst node; lane l owns float4 chunk l.
// neigh[n] = tf32( (1/max(deg,1)) * sum w_e * h[src_e] )
// ---------------------------------------------------------------------------
__global__ void k_gather(const float* __restrict__ h,
                         float* __restrict__ neigh) {
    const int n = (blockIdx.x * blockDim.x + threadIdx.x) >> 5;
    if (n >= NN) return;
    const int lane = threadIdx.x & 31;

    const int start = g_rowstart[n];
    const int end   = g_rowstart[n + 1];
    const float4* h4 = reinterpret_cast<const float4*>(h);

    float4 acc0 = make_float4(0.f, 0.f, 0.f, 0.f);
    float4 acc1 = make_float4(0.f, 0.f, 0.f, 0.f);

    int i = start;
    for (; i + 3 < end; i += 4) {
        int2 e0 = g_elist[i];
        int2 e1 = g_elist[i + 1];
        int2 e2 = g_elist[i + 2];
        int2 e3 = g_elist[i + 3];
        float4 v0 = h4[(size_t)e0.x * 32 + lane];
        float4 v1 = h4[(size_t)e1.x * 32 + lane];
        float4 v2 = h4[(size_t)e2.x * 32 + lane];
        float4 v3 = h4[(size_t)e3.x * 32 + lane];
        float w0 = __int_as_float(e0.y), w1 = __int_as_float(e1.y);
        float w2 = __int_as_float(e2.y), w3 = __int_as_float(e3.y);
        acc0.x = fmaf(w0, v0.x, acc0.x); acc0.y = fmaf(w0, v0.y, acc0.y);
        acc0.z = fmaf(w0, v0.z, acc0.z); acc0.w = fmaf(w0, v0.w, acc0.w);
        acc1.x = fmaf(w1, v1.x, acc1.x); acc1.y = fmaf(w1, v1.y, acc1.y);
        acc1.z = fmaf(w1, v1.z, acc1.z); acc1.w = fmaf(w1, v1.w, acc1.w);
        acc0.x = fmaf(w2, v2.x, acc0.x); acc0.y = fmaf(w2, v2.y, acc0.y);
        acc0.z = fmaf(w2, v2.z, acc0.z); acc0.w = fmaf(w2, v2.w, acc0.w);
        acc1.x = fmaf(w3, v3.x, acc1.x); acc1.y = fmaf(w3, v3.y, acc1.y);
        acc1.z = fmaf(w3, v3.z, acc1.z); acc1.w = fmaf(w3, v3.w, acc1.w);
    }
    for (; i < end; i++) {
        int2 e0 = g_elist[i];
        float w0 = __int_as_float(e0.y);
        float4 v0 = h4[(size_t)e0.x * 32 + lane];
        acc0.x = fmaf(w0, v0.x, acc0.x); acc0.y = fmaf(w0, v0.y, acc0.y);
        acc0.z = fmaf(w0, v0.z, acc0.z); acc0.w = fmaf(w0, v0.w, acc0.w);
    }

    int deg = end - start;
    float inv = 1.0f / (float)max(deg, 1);
    float4 r;
    r.x = f2tf32((acc0.x + acc1.x) * inv);
    r.y = f2tf32((acc0.y + acc1.y) * inv);
    r.z = f2tf32((acc0.z + acc1.z) * inv);
    r.w = f2tf32((acc0.w + acc1.w) * inv);
    reinterpret_cast<float4*>(neigh)[(size_t)n * 32 + lane] = r;
}

// ---------------------------------------------------------------------------
// Fused SAGE GEMM, tf32 tensor cores.
// cp.async double-buffered A, register-prefetched B, occupancy 2,
// 2 barriers per k-tile. A operands may be raw fp32 (HMMA truncates to tf32).
// Swizzle: addr = r*32 + (k ^ ((r&7)<<2)) — conflict-free for STS.128 staging
// and the mma fragment LDS.32 pattern.
// ---------------------------------------------------------------------------
#define SWZ(r, k) (((r) << 5) + ((k) ^ (((r) & 7) << 2)))

template <bool RELU, bool ROUND_OUT>
__global__ void __launch_bounds__(256, 2)
k_gemm_tf32(const float* __restrict__ X,
            const float* __restrict__ S,
            const float* __restrict__ Wcat,   // [128][256] tf32
            const float* __restrict__ bias,
            float* __restrict__ out) {
    __shared__ float As[2][128 * 32];   // 32 KB
    __shared__ float Bs[128 * 32];      // 16 KB  (total 48 KB exactly)

    const int tid  = threadIdx.x;
    const int bm0  = blockIdx.x * 128;
    const int wid  = tid >> 5;
    const int lane = tid & 31;
    const int wm   = (wid & 1) * 64;
    const int wn   = (wid >> 1) * 32;
    const int gr   = lane >> 2;
    const int gc   = lane & 3;

    int rr[4], cc4[4];
#pragma unroll
    for (int l = 0; l < 4; l++) {
        int idx = l * 256 + tid;
        rr[l]  = idx >> 3;
        cc4[l] = idx & 7;
    }

    const float4* wcat4 = reinterpret_cast<const float4*>(Wcat);

    float acc[4][4][4];
#pragma unroll
    for (int mi = 0; mi < 4; mi++)
#pragma unroll
        for (int ni = 0; ni < 4; ni++)
#pragma unroll
            for (int c = 0; c < 4; c++) acc[mi][ni][c] = 0.f;

    auto issueA = [&](int kt, int buf) {
        const float* base = (kt < 4) ? X : S;
        const int kb = (kt & 3) * 32;
#pragma unroll
        for (int l = 0; l < 4; l++) {
            int grow = bm0 + rr[l];
            bool p = grow < NN;
            int gsafe = p ? grow : 0;
            const float* gp = base + (size_t)gsafe * 128 + kb + cc4[l] * 4;
            cp16(&As[buf][SWZ(rr[l], cc4[l] * 4)], gp, p);
        }
        cp_commit();
    };

    float4 breg[4];
    auto loadB = [&](int kt) {
#pragma unroll
        for (int l = 0; l < 4; l++)
            breg[l] = wcat4[(size_t)rr[l] * 64 + kt * 8 + cc4[l]];
    };

    issueA(0, 0);
    loadB(0);

#pragma unroll 1
    for (int kt = 0; kt < 8; kt++) {
        cp_wait0();
        __syncthreads();          // As[kt&1] visible; prev mma done (Bs, As free)

        // stage current B from regs, prefetch next B, start next A copy
#pragma unroll
        for (int l = 0; l < 4; l++)
            *reinterpret_cast<float4*>(&Bs[SWZ(rr[l], cc4[l] * 4)]) = breg[l];
        if (kt < 7) {
            issueA(kt + 1, (kt + 1) & 1);   // overlaps with mma below
            loadB(kt + 1);
        }

        __syncthreads();          // Bs visible

        const float* Ab = As[kt & 1];
#pragma unroll
        for (int ks = 0; ks < 4; ks++) {
            const int k0 = ks * 8;

            unsigned a[4][4];
#pragma unroll
            for (int mi = 0; mi < 4; mi++) {
                int r = wm + mi * 16 + gr;
                a[mi][0] = __float_as_uint(Ab[SWZ(r,     k0 + gc)]);
                a[mi][1] = __float_as_uint(Ab[SWZ(r + 8, k0 + gc)]);
                a[mi][2] = __float_as_uint(Ab[SWZ(r,     k0 + gc + 4)]);
                a[mi][3] = __float_as_uint(Ab[SWZ(r + 8, k0 + gc + 4)]);
            }

            unsigned b[4][2];
#pragma unroll
            for (int ni = 0; ni < 4; ni++) {
                int n = wn + ni * 8 + gr;
                b[ni][0] = __float_as_uint(Bs[SWZ(n, k0 + gc)]);
                b[ni][1] = __float_as_uint(Bs[SWZ(n, k0 + gc + 4)]);
            }

#pragma unroll
            for (int mi = 0; mi < 4; mi++)
#pragma unroll
                for (int ni = 0; ni < 4; ni++)
                    mma_tf32(acc[mi][ni], a[mi], b[ni]);
        }
    }

    // --- epilogue
#pragma unroll
    for (int ni = 0; ni < 4; ni++) {
        int col = wn + ni * 8 + gc * 2;
        float b0 = bias[col];
        float b1 = bias[col + 1];
#pragma unroll
        for (int mi = 0; mi < 4; mi++) {
            int r0 = bm0 + wm + mi * 16 + gr;
            float2 v0, v1;
            v0.x = acc[mi][ni][0] + b0;
            v0.y = acc[mi][ni][1] + b1;
            v1.x = acc[mi][ni][2] + b0;
            v1.y = acc[mi][ni][3] + b1;
            if (RELU) {
                v0.x = fmaxf(v0.x, 0.f); v0.y = fmaxf(v0.y, 0.f);
                v1.x = fmaxf(v1.x, 0.f); v1.y = fmaxf(v1.y, 0.f);
            }
            if (ROUND_OUT) {
                v0.x = f2tf32(v0.x); v0.y = f2tf32(v0.y);
                v1.x = f2tf32(v1.x); v1.y = f2tf32(v1.y);
            }
            if (r0 < NN)
                *reinterpret_cast<float2*>(&out[(size_t)r0 * 128 + col]) = v0;
            if (r0 + 8 < NN)
                *reinterpret_cast<float2*>(&out[(size_t)(r0 + 8) * 128 + col]) = v1;
        }
    }
}

// ---------------------------------------------------------------------------
// launch  (k_gather is the 4th kernel launch -> lands in ncu's capture slot)
// ---------------------------------------------------------------------------
extern "C" void kernel_launch(void* const* d_in, const int* in_sizes, int n_in,
                              void* d_out, int out_size) {
    const float* in_feat = (const float*)d_in[0];
    const float* weights = (const float*)d_in[1];
    const int*   src     = (const int*)d_in[2];
    const int*   dst     = (const int*)d_in[3];
    const float* Ws1     = (const float*)d_in[4];
    const float* b1      = (const float*)d_in[5];
    const float* Wn1     = (const float*)d_in[6];
    const float* Ws2     = (const float*)d_in[7];
    const float* b2      = (const float*)d_in[8];
    const float* Wn2     = (const float*)d_in[9];
    float* out = (float*)d_out;

    void *p_s, *p_h1, *p_cnt, *p_w, *p_state;
    cudaGetSymbolAddress(&p_s, g_s);
    cudaGetSymbolAddress(&p_h1, g_h1);
    cudaGetSymbolAddress(&p_cnt, g_cnt);
    cudaGetSymbolAddress(&p_w, g_wcat);
    cudaGetSymbolAddress(&p_state, g_state);
    float* s  = (float*)p_s;
    float* h1 = (float*)p_h1;
    float* w0 = (float*)p_w;
    float* w1 = w0 + 128 * 256;

    const int eb = (EE + 255) / 256;
    const int gather_blocks = (NN * 32 + 255) / 256;
    const int gemm_blocks = (NN + 127) / 128;

    // --- CSR build
    cudaMemsetAsync(p_cnt, 0, NN * sizeof(int), 0);
    cudaMemsetAsync(p_state, 0, SCAN_BLOCKS * sizeof(unsigned long long), 0);
    k_hist<<<eb, 256>>>(dst);                     // launch 1
    k_scan<<<SCAN_BLOCKS, 256>>>();               // launch 2
    k_fill<<<eb, 256>>>(src, dst, weights);       // launch 3

    // --- Layer 1
    k_gather<<<gather_blocks, 256>>>(in_feat, s); // launch 4  (profiled)
    k_cvtw<<<256, 256>>>(Ws1, Wn1, Ws2, Wn2);     // launch 5
    k_gemm_tf32<true, true><<<gemm_blocks, 256>>>(in_feat, s, w0, b1, h1);

    // --- Layer 2
    k_gather<<<gather_blocks, 256>>>(h1, s);
    k_gemm_tf32<false, false><<<gemm_blocks, 256>>>(h1, s, w1, b2, out);
}

// round 8
// speedup vs baseline: 1.2325x; 1.1497x over previous
#include <cuda_runtime.h>
#include <cuda_fp16.h>
#include <cstdint>

#define NN 100000
#define EE 1600000
#define SCAN_BLOCKS 391   // ceil(NN/256)

// Scratch (static device globals — no allocation in kernel_launch)
__device__ float  g_s[(size_t)NN * 128];    // neigh buffer (tf32-RNA rounded)
__device__ float  g_h1[(size_t)NN * 128];   // layer-1 output (tf32-RNA rounded)
__device__ __half g_xh[(size_t)NN * 128];   // fp16 in_feat (gather-1 input)
__device__ __half g_hh[(size_t)NN * 128];   // fp16 h1 (gather-2 input)
__device__ float  g_wcat[2][128 * 256];     // tf32 [Ws | Wn] per layer, row-major
__device__ int    g_cnt[NN];
__device__ unsigned long long g_state[SCAN_BLOCKS];
__device__ int    g_rowstart[NN + 1];
__device__ int    g_cursor[NN];
__device__ int2   g_elist[EE];              // {src, weight_bits} grouped by dst

// ---------------------------------------------------------------------------
// helpers
// ---------------------------------------------------------------------------
__device__ __forceinline__ float f2tf32(float x) {
    unsigned r;
    asm("cvt.rna.tf32.f32 %0, %1;" : "=r"(r) : "f"(x));
    return __uint_as_float(r);
}

__device__ __forceinline__ void mma_tf32(float c[4],
                                         const unsigned a[4],
                                         const unsigned b[2]) {
    asm volatile(
        "mma.sync.aligned.m16n8k8.row.col.f32.tf32.tf32.f32 "
        "{%0,%1,%2,%3}, {%4,%5,%6,%7}, {%8,%9}, {%0,%1,%2,%3};"
        : "+f"(c[0]), "+f"(c[1]), "+f"(c[2]), "+f"(c[3])
        : "r"(a[0]), "r"(a[1]), "r"(a[2]), "r"(a[3]),
          "r"(b[0]), "r"(b[1]));
}

__device__ __forceinline__ void cp16(float* sdst, const float* gsrc, bool pred) {
    unsigned s = (unsigned)__cvta_generic_to_shared(sdst);
    int sz = pred ? 16 : 0;
    asm volatile("cp.async.cg.shared.global [%0], [%1], 16, %2;"
                 :: "r"(s), "l"(gsrc), "r"(sz));
}
__device__ __forceinline__ void cp_commit() {
    asm volatile("cp.async.commit_group;");
}
__device__ __forceinline__ void cp_wait0() {
    asm volatile("cp.async.wait_group 0;");
}

// ---------------------------------------------------------------------------
// prep: in_feat -> fp16 copy, weight concat/tf32, zero cnt/state
// grid: 12500 x 256 (3.2M threads, one float4 each)
// ---------------------------------------------------------------------------
__global__ void k_prep(const float* __restrict__ x,
                       const float* __restrict__ Ws1, const float* __restrict__ Wn1,
                       const float* __restrict__ Ws2, const float* __restrict__ Wn2) {
    int i = blockIdx.x * blockDim.x + threadIdx.x;

    if (i < NN * 32) {   // fp16 feature copy
        float4 v = reinterpret_cast<const float4*>(x)[i];
        __half2 h0 = __floats2half2_rn(v.x, v.y);
        __half2 h1 = __floats2half2_rn(v.z, v.w);
        reinterpret_cast<__half2*>(g_xh)[i * 2]     = h0;
        reinterpret_cast<__half2*>(g_xh)[i * 2 + 1] = h1;
    }
    if (i < 65536) {
        int l   = i >> 15;
        int rem = i & 32767;     // f*256 + k
        int f   = rem >> 8;
        int k   = rem & 255;
        const float* W = l ? (k < 128 ? Ws2 : Wn2) : (k < 128 ? Ws1 : Wn1);
        g_wcat[l][rem] = f2tf32(W[f * 128 + (k & 127)]);
    }
    if (i < NN) g_cnt[i] = 0;
    if (i < SCAN_BLOCKS) g_state[i] = 0ULL;
}

// ---------------------------------------------------------------------------
// CSR build: histogram -> decoupled-lookback scan -> fill
// ---------------------------------------------------------------------------
__global__ void k_hist(const int* __restrict__ dst) {
    int e = blockIdx.x * blockDim.x + threadIdx.x;
    if (e < EE) atomicAdd(&g_cnt[dst[e]], 1);
}

__global__ void k_scan() {
    __shared__ int sm[256];
    __shared__ int s_prefix;
    const int b = blockIdx.x;
    const int t = threadIdx.x;
    const int i = b * 256 + t;

    int v = (i < NN) ? g_cnt[i] : 0;
    sm[t] = v;
    __syncthreads();
#pragma unroll
    for (int ofs = 1; ofs < 256; ofs <<= 1) {
        int tv = (t >= ofs) ? sm[t - ofs] : 0;
        __syncthreads();
        sm[t] += tv;
        __syncthreads();
    }
    int incl  = sm[t];
    int total = sm[255];

    if (t == 0) {
        if (b == 0) {
            atomicExch(&g_state[0], (2ULL << 32) | (unsigned)total);
            s_prefix = 0;
        } else {
            atomicExch(&g_state[b], (1ULL << 32) | (unsigned)total);
            int run = 0;
            for (int p = b - 1; p >= 0; p--) {
                unsigned long long s;
                do { s = atomicAdd(&g_state[p], 0ULL); } while ((s >> 32) == 0ULL);
                run += (int)(unsigned)s;
                if ((s >> 32) == 2ULL) break;
            }
            s_prefix = run;
            atomicExch(&g_state[b], (2ULL << 32) | (unsigned)(run + total));
        }
    }
    __syncthreads();

    if (i < NN) {
        int rs = s_prefix + incl - v;
        g_rowstart[i] = rs;
        g_cursor[i]   = rs;
    }
    if (i == 0) g_rowstart[NN] = EE;
}

__global__ void k_fill(const int* __restrict__ src,
                       const int* __restrict__ dst,
                       const float* __restrict__ w) {
    int e = blockIdx.x * blockDim.x + threadIdx.x;
    if (e >= EE) return;
    int pos = atomicAdd(&g_cursor[dst[e]], 1);
    g_elist[pos] = make_int2(src[e], __float_as_int(w[e]));
}

// ---------------------------------------------------------------------------
// Gather-aggregate over fp16 features: one warp per dst node.
// Lane l owns 4 consecutive features (8 bytes). fp32 accumulation.
// neigh[n] = tf32_rna( (1/max(deg,1)) * sum w_e * h[src_e] )
// ---------------------------------------------------------------------------
__global__ void k_gather(const __half* __restrict__ h,
                         float* __restrict__ neigh) {
    const int n = (blockIdx.x * blockDim.x + threadIdx.x) >> 5;
    if (n >= NN) return;
    const int lane = threadIdx.x & 31;

    const int start = g_rowstart[n];
    const int end   = g_rowstart[n + 1];
    const uint2* h2 = reinterpret_cast<const uint2*>(h);  // 8B = 4 halves

    float a0 = 0.f, a1 = 0.f, a2 = 0.f, a3 = 0.f;

    auto accum = [&](int2 e) {
        float w = __int_as_float(e.y);
        uint2 raw = h2[(size_t)e.x * 32 + lane];
        __half2 p0 = *reinterpret_cast<__half2*>(&raw.x);
        __half2 p1 = *reinterpret_cast<__half2*>(&raw.y);
        float2 f0 = __half22float2(p0);
        float2 f1 = __half22float2(p1);
        a0 = fmaf(w, f0.x, a0);
        a1 = fmaf(w, f0.y, a1);
        a2 = fmaf(w, f1.x, a2);
        a3 = fmaf(w, f1.y, a3);
    };

    int i = start;
    for (; i + 3 < end; i += 4) {
        int2 e0 = g_elist[i];
        int2 e1 = g_elist[i + 1];
        int2 e2 = g_elist[i + 2];
        int2 e3 = g_elist[i + 3];
        accum(e0); accum(e1); accum(e2); accum(e3);
    }
    for (; i < end; i++) accum(g_elist[i]);

    int deg = end - start;
    float inv = 1.0f / (float)max(deg, 1);
    float4 r;
    r.x = f2tf32(a0 * inv);
    r.y = f2tf32(a1 * inv);
    r.z = f2tf32(a2 * inv);
    r.w = f2tf32(a3 * inv);
    reinterpret_cast<float4*>(neigh)[(size_t)n * 32 + lane] = r;
}

// ---------------------------------------------------------------------------
// Fused SAGE GEMM, tf32 mma.sync, cp.async double-buffered A,
// register-prefetched B, occupancy 2 (48 KB static smem), 2 barriers/k-tile.
// Swizzle: addr = r*32 + (k ^ ((r&7)<<2)).
// ---------------------------------------------------------------------------
#define SWZ(r, k) (((r) << 5) + ((k) ^ (((r) & 7) << 2)))

template <bool RELU, bool ROUND_OUT, bool WRITE_H>
__global__ void __launch_bounds__(256, 2)
k_gemm_tf32(const float* __restrict__ X,
            const float* __restrict__ S,
            const float* __restrict__ Wcat,   // [128][256] tf32
            const float* __restrict__ bias,
            float* __restrict__ out,
            __half* __restrict__ outh) {
    __shared__ float As[2][128 * 32];   // 32 KB
    __shared__ float Bs[128 * 32];      // 16 KB

    const int tid  = threadIdx.x;
    const int bm0  = blockIdx.x * 128;
    const int wid  = tid >> 5;
    const int lane = tid & 31;
    const int wm   = (wid & 1) * 64;
    const int wn   = (wid >> 1) * 32;
    const int gr   = lane >> 2;
    const int gc   = lane & 3;

    int rr[4], cc4[4];
#pragma unroll
    for (int l = 0; l < 4; l++) {
        int idx = l * 256 + tid;
        rr[l]  = idx >> 3;
        cc4[l] = idx & 7;
    }

    const float4* wcat4 = reinterpret_cast<const float4*>(Wcat);

    float acc[4][4][4];
#pragma unroll
    for (int mi = 0; mi < 4; mi++)
#pragma unroll
        for (int ni = 0; ni < 4; ni++)
#pragma unroll
            for (int c = 0; c < 4; c++) acc[mi][ni][c] = 0.f;

    auto issueA = [&](int kt, int buf) {
        const float* base = (kt < 4) ? X : S;
        const int kb = (kt & 3) * 32;
#pragma unroll
        for (int l = 0; l < 4; l++) {
            int grow = bm0 + rr[l];
            bool p = grow < NN;
            int gsafe = p ? grow : 0;
            const float* gp = base + (size_t)gsafe * 128 + kb + cc4[l] * 4;
            cp16(&As[buf][SWZ(rr[l], cc4[l] * 4)], gp, p);
        }
        cp_commit();
    };

    float4 breg[4];
    auto loadB = [&](int kt) {
#pragma unroll
        for (int l = 0; l < 4; l++)
            breg[l] = wcat4[(size_t)rr[l] * 64 + kt * 8 + cc4[l]];
    };

    issueA(0, 0);
    loadB(0);

#pragma unroll 1
    for (int kt = 0; kt < 8; kt++) {
        cp_wait0();
        __syncthreads();          // As[kt&1] visible; prev mma done

#pragma unroll
        for (int l = 0; l < 4; l++)
            *reinterpret_cast<float4*>(&Bs[SWZ(rr[l], cc4[l] * 4)]) = breg[l];
        if (kt < 7) {
            issueA(kt + 1, (kt + 1) & 1);   // overlaps with mma below
            loadB(kt + 1);
        }

        __syncthreads();          // Bs visible

        const float* Ab = As[kt & 1];
#pragma unroll
        for (int ks = 0; ks < 4; ks++) {
            const int k0 = ks * 8;

            unsigned a[4][4];
#pragma unroll
            for (int mi = 0; mi < 4; mi++) {
                int r = wm + mi * 16 + gr;
                a[mi][0] = __float_as_uint(Ab[SWZ(r,     k0 + gc)]);
                a[mi][1] = __float_as_uint(Ab[SWZ(r + 8, k0 + gc)]);
                a[mi][2] = __float_as_uint(Ab[SWZ(r,     k0 + gc + 4)]);
                a[mi][3] = __float_as_uint(Ab[SWZ(r + 8, k0 + gc + 4)]);
            }

            unsigned b[4][2];
#pragma unroll
            for (int ni = 0; ni < 4; ni++) {
                int n = wn + ni * 8 + gr;
                b[ni][0] = __float_as_uint(Bs[SWZ(n, k0 + gc)]);
                b[ni][1] = __float_as_uint(Bs[SWZ(n, k0 + gc + 4)]);
            }

#pragma unroll
            for (int mi = 0; mi < 4; mi++)
#pragma unroll
                for (int ni = 0; ni < 4; ni++)
                    mma_tf32(acc[mi][ni], a[mi], b[ni]);
        }
    }

    // --- epilogue
#pragma unroll
    for (int ni = 0; ni < 4; ni++) {
        int col = wn + ni * 8 + gc * 2;
        float b0 = bias[col];
        float b1 = bias[col + 1];
#pragma unroll
        for (int mi = 0; mi < 4; mi++) {
            int r0 = bm0 + wm + mi * 16 + gr;
            float2 v0, v1;
            v0.x = acc[mi][ni][0] + b0;
            v0.y = acc[mi][ni][1] + b1;
            v1.x = acc[mi][ni][2] + b0;
            v1.y = acc[mi][ni][3] + b1;
            if (RELU) {
                v0.x = fmaxf(v0.x, 0.f); v0.y = fmaxf(v0.y, 0.f);
                v1.x = fmaxf(v1.x, 0.f); v1.y = fmaxf(v1.y, 0.f);
            }
            if (r0 < NN) {
                if (WRITE_H)
                    *reinterpret_cast<__half2*>(&outh[(size_t)r0 * 128 + col]) =
                        __floats2half2_rn(v0.x, v0.y);
                float2 w0 = v0;
                if (ROUND_OUT) { w0.x = f2tf32(w0.x); w0.y = f2tf32(w0.y); }
                *reinterpret_cast<float2*>(&out[(size_t)r0 * 128 + col]) = w0;
            }
            if (r0 + 8 < NN) {
                if (WRITE_H)
                    *reinterpret_cast<__half2*>(&outh[(size_t)(r0 + 8) * 128 + col]) =
                        __floats2half2_rn(v1.x, v1.y);
                float2 w1 = v1;
                if (ROUND_OUT) { w1.x = f2tf32(w1.x); w1.y = f2tf32(w1.y); }
                *reinterpret_cast<float2*>(&out[(size_t)(r0 + 8) * 128 + col]) = w1;
            }
        }
    }
}

// ---------------------------------------------------------------------------
// launch  (gemm1 is kernel launch #6 -> ncu capture slot)
// ---------------------------------------------------------------------------
extern "C" void kernel_launch(void* const* d_in, const int* in_sizes, int n_in,
                              void* d_out, int out_size) {
    const float* in_feat = (const float*)d_in[0];
    const float* weights = (const float*)d_in[1];
    const int*   src     = (const int*)d_in[2];
    const int*   dst     = (const int*)d_in[3];
    const float* Ws1     = (const float*)d_in[4];
    const float* b1      = (const float*)d_in[5];
    const float* Wn1     = (const float*)d_in[6];
    const float* Ws2     = (const float*)d_in[7];
    const float* b2      = (const float*)d_in[8];
    const float* Wn2     = (const float*)d_in[9];
    float* out = (float*)d_out;

    void *p_s, *p_h1, *p_xh, *p_hh, *p_w;
    cudaGetSymbolAddress(&p_s, g_s);
    cudaGetSymbolAddress(&p_h1, g_h1);
    cudaGetSymbolAddress(&p_xh, g_xh);
    cudaGetSymbolAddress(&p_hh, g_hh);
    cudaGetSymbolAddress(&p_w, g_wcat);
    float*  s  = (float*)p_s;
    float*  h1 = (float*)p_h1;
    __half* xh = (__half*)p_xh;
    __half* hh = (__half*)p_hh;
    float*  w0 = (float*)p_w;
    float*  w1 = w0 + 128 * 256;

    const int eb = (EE + 255) / 256;
    const int prep_blocks = (NN * 32 + 255) / 256;    // 12500
    const int gather_blocks = (NN * 32 + 255) / 256;  // 1 warp per node
    const int gemm_blocks = (NN + 127) / 128;

    k_prep<<<prep_blocks, 256>>>(in_feat, Ws1, Wn1, Ws2, Wn2);  // 1
    k_hist<<<eb, 256>>>(dst);                                   // 2
    k_scan<<<SCAN_BLOCKS, 256>>>();                             // 3
    k_fill<<<eb, 256>>>(src, dst, weights);                     // 4

    // Layer 1
    k_gather<<<gather_blocks, 256>>>(xh, s);                    // 5
    k_gemm_tf32<true, true, true><<<gemm_blocks, 256>>>(        // 6 (profiled)
        in_feat, s, w0, b1, h1, hh);

    // Layer 2
    k_gather<<<gather_blocks, 256>>>(hh, s);                    // 7
    k_gemm_tf32<false, false, false><<<gemm_blocks, 256>>>(     // 8
        h1, s, w1, b2, out, nullptr);
}

// round 9
// speedup vs baseline: 1.5549x; 1.2616x over previous
#include <cuda_runtime.h>
#include <cuda_fp16.h>
#include <cstdint>

#define NN 100000
#define EE 1600000
#define SCAN_BLOCKS 391   // ceil(NN/256)

// Scratch (static device globals — no allocation in kernel_launch)
__device__ __half g_xh[(size_t)NN * 128];   // fp16 in_feat
__device__ __half g_hh[(size_t)NN * 128];   // fp16 h1 (layer-1 output)
__device__ __half g_sh[(size_t)NN * 128];   // fp16 neigh buffer
__device__ __half g_wcat[2][128 * 256];     // fp16 [Ws | Wn] per layer, row-major
__device__ int    g_cnt[NN];
__device__ unsigned long long g_state[SCAN_BLOCKS];
__device__ int    g_rowstart[NN + 1];
__device__ int    g_cursor[NN];
__device__ int2   g_elist[EE];              // {src, weight_bits} grouped by dst

// ---------------------------------------------------------------------------
// helpers
// ---------------------------------------------------------------------------
__device__ __forceinline__ void mma_fp16(float c[4],
                                         const unsigned a[4],
                                         const unsigned b[2]) {
    asm volatile(
        "mma.sync.aligned.m16n8k16.row.col.f32.f16.f16.f32 "
        "{%0,%1,%2,%3}, {%4,%5,%6,%7}, {%8,%9}, {%0,%1,%2,%3};"
        : "+f"(c[0]), "+f"(c[1]), "+f"(c[2]), "+f"(c[3])
        : "r"(a[0]), "r"(a[1]), "r"(a[2]), "r"(a[3]),
          "r"(b[0]), "r"(b[1]));
}

__device__ __forceinline__ void cp16(void* sdst, const void* gsrc, bool pred) {
    unsigned s = (unsigned)__cvta_generic_to_shared(sdst);
    int sz = pred ? 16 : 0;
    asm volatile("cp.async.cg.shared.global [%0], [%1], 16, %2;"
                 :: "r"(s), "l"(gsrc), "r"(sz));
}
__device__ __forceinline__ void cp_commit() {
    asm volatile("cp.async.commit_group;");
}
__device__ __forceinline__ void cp_wait0() {
    asm volatile("cp.async.wait_group 0;");
}

// ---------------------------------------------------------------------------
// prep: in_feat -> fp16, weights -> fp16 concat, zero cnt/state
// ---------------------------------------------------------------------------
__global__ void k_prep(const float* __restrict__ x,
                       const float* __restrict__ Ws1, const float* __restrict__ Wn1,
                       const float* __restrict__ Ws2, const float* __restrict__ Wn2) {
    int i = blockIdx.x * blockDim.x + threadIdx.x;

    if (i < NN * 32) {   // fp16 feature copy (one float4 -> 4 halves)
        float4 v = reinterpret_cast<const float4*>(x)[i];
        __half2 h0 = __floats2half2_rn(v.x, v.y);
        __half2 h1 = __floats2half2_rn(v.z, v.w);
        reinterpret_cast<__half2*>(g_xh)[i * 2]     = h0;
        reinterpret_cast<__half2*>(g_xh)[i * 2 + 1] = h1;
    }
    if (i < 65536) {
        int l   = i >> 15;
        int rem = i & 32767;     // f*256 + k
        int f   = rem >> 8;
        int k   = rem & 255;
        const float* W = l ? (k < 128 ? Ws2 : Wn2) : (k < 128 ? Ws1 : Wn1);
        g_wcat[l][rem] = __float2half_rn(W[f * 128 + (k & 127)]);
    }
    if (i < NN) g_cnt[i] = 0;
    if (i < SCAN_BLOCKS) g_state[i] = 0ULL;
}

// ---------------------------------------------------------------------------
// CSR build: histogram -> decoupled-lookback scan -> fill
// ---------------------------------------------------------------------------
__global__ void k_hist(const int* __restrict__ dst) {
    int e = blockIdx.x * blockDim.x + threadIdx.x;
    if (e < EE) atomicAdd(&g_cnt[dst[e]], 1);
}

__global__ void k_scan() {
    __shared__ int sm[256];
    __shared__ int s_prefix;
    const int b = blockIdx.x;
    const int t = threadIdx.x;
    const int i = b * 256 + t;

    int v = (i < NN) ? g_cnt[i] : 0;
    sm[t] = v;
    __syncthreads();
#pragma unroll
    for (int ofs = 1; ofs < 256; ofs <<= 1) {
        int tv = (t >= ofs) ? sm[t - ofs] : 0;
        __syncthreads();
        sm[t] += tv;
        __syncthreads();
    }
    int incl  = sm[t];
    int total = sm[255];

    if (t == 0) {
        if (b == 0) {
            atomicExch(&g_state[0], (2ULL << 32) | (unsigned)total);
            s_prefix = 0;
        } else {
            atomicExch(&g_state[b], (1ULL << 32) | (unsigned)total);
            int run = 0;
            for (int p = b - 1; p >= 0; p--) {
                unsigned long long s;
                do { s = atomicAdd(&g_state[p], 0ULL); } while ((s >> 32) == 0ULL);
                run += (int)(unsigned)s;
                if ((s >> 32) == 2ULL) break;
            }
            s_prefix = run;
            atomicExch(&g_state[b], (2ULL << 32) | (unsigned)(run + total));
        }
    }
    __syncthreads();

    if (i < NN) {
        int rs = s_prefix + incl - v;
        g_rowstart[i] = rs;
        g_cursor[i]   = rs;
    }
    if (i == 0) g_rowstart[NN] = EE;
}

__global__ void k_fill(const int* __restrict__ src,
                       const int* __restrict__ dst,
                       const float* __restrict__ w) {
    int e = blockIdx.x * blockDim.x + threadIdx.x;
    if (e >= EE) return;
    int pos = atomicAdd(&g_cursor[dst[e]], 1);
    g_elist[pos] = make_int2(src[e], __float_as_int(w[e]));
}

// ---------------------------------------------------------------------------
// Gather-aggregate over fp16 features: one warp per dst node.
// Lane l owns 4 consecutive features (8 bytes). fp32 accumulation,
// fp16 output (the store IS the rounding).
// ---------------------------------------------------------------------------
__global__ void k_gather(const __half* __restrict__ h,
                         __half* __restrict__ neigh) {
    const int n = (blockIdx.x * blockDim.x + threadIdx.x) >> 5;
    if (n >= NN) return;
    const int lane = threadIdx.x & 31;

    const int start = g_rowstart[n];
    const int end   = g_rowstart[n + 1];
    const uint2* h2 = reinterpret_cast<const uint2*>(h);  // 8B = 4 halves

    float a0 = 0.f, a1 = 0.f, a2 = 0.f, a3 = 0.f;

    auto accum = [&](int2 e) {
        float w = __int_as_float(e.y);
        uint2 raw = h2[(size_t)e.x * 32 + lane];
        __half2 p0 = *reinterpret_cast<__half2*>(&raw.x);
        __half2 p1 = *reinterpret_cast<__half2*>(&raw.y);
        float2 f0 = __half22float2(p0);
        float2 f1 = __half22float2(p1);
        a0 = fmaf(w, f0.x, a0);
        a1 = fmaf(w, f0.y, a1);
        a2 = fmaf(w, f1.x, a2);
        a3 = fmaf(w, f1.y, a3);
    };

    int i = start;
    for (; i + 3 < end; i += 4) {
        int2 e0 = g_elist[i];
        int2 e1 = g_elist[i + 1];
        int2 e2 = g_elist[i + 2];
        int2 e3 = g_elist[i + 3];
        accum(e0); accum(e1); accum(e2); accum(e3);
    }
    for (; i < end; i++) accum(g_elist[i]);

    int deg = end - start;
    float inv = 1.0f / (float)max(deg, 1);
    __half2 r0 = __floats2half2_rn(a0 * inv, a1 * inv);
    __half2 r1 = __floats2half2_rn(a2 * inv, a3 * inv);
    uint2 packed;
    packed.x = *reinterpret_cast<unsigned*>(&r0);
    packed.y = *reinterpret_cast<unsigned*>(&r1);
    reinterpret_cast<uint2*>(neigh)[(size_t)n * 32 + lane] = packed;
}

// ---------------------------------------------------------------------------
// Fused SAGE GEMM, fp16 mma.sync.m16n8k16, fp32 accumulate.
//   out[n][f] = act( [X|S](fp16, K=256) x Wcat[128,256]^T + bias )
// BM=128, BN=128, BK=64 halves; 4 K-chunks. cp.async double-buffered A,
// register-prefetched B, occupancy 2 (48 KB), 2 barriers per chunk.
// Smem in 4B words (half2): SWZ(r,w) = r*32 + (w ^ ((r&7)<<2)) — conflict-free
// for 16B staging stores and the half2 fragment loads.
// ---------------------------------------------------------------------------
#define SWZ(r, w) (((r) << 5) + ((w) ^ (((r) & 7) << 2)))

template <bool RELU, bool OUT_HALF>
__global__ void __launch_bounds__(256, 2)
k_gemm_fp16(const __half* __restrict__ X,
            const __half* __restrict__ S,
            const __half* __restrict__ Wcat,   // [128][256] fp16
            const float* __restrict__ bias,
            float* __restrict__ out,
            __half* __restrict__ outh) {
    __shared__ unsigned As[2][128 * 32];   // 16 KB each (words = half2)
    __shared__ unsigned Bs[128 * 32];      // 16 KB

    const int tid  = threadIdx.x;
    const int bm0  = blockIdx.x * 128;
    const int wid  = tid >> 5;
    const int lane = tid & 31;
    const int wm   = (wid & 1) * 64;
    const int wn   = (wid >> 1) * 32;
    const int gr   = lane >> 2;
    const int gc   = lane & 3;

    // staging coords: idx = l*256+tid -> r = idx>>3 (0..127), c8 = idx&7
    int rr[4], cc8[4];
#pragma unroll
    for (int l = 0; l < 4; l++) {
        int idx = l * 256 + tid;
        rr[l]  = idx >> 3;
        cc8[l] = idx & 7;
    }

    const uint4* wcat4 = reinterpret_cast<const uint4*>(Wcat);

    float acc[4][4][4];
#pragma unroll
    for (int mi = 0; mi < 4; mi++)
#pragma unroll
        for (int ni = 0; ni < 4; ni++)
#pragma unroll
            for (int c = 0; c < 4; c++) acc[mi][ni][c] = 0.f;

    // A chunk c (0..3): halves [c*64, c*64+64); c<2 from X, else from S
    auto issueA = [&](int c, int buf) {
        const __half* base = (c < 2) ? X : S;
        const int kb = (c & 1) * 64;   // half offset within the 128-half row
#pragma unroll
        for (int l = 0; l < 4; l++) {
            int grow = bm0 + rr[l];
            bool p = grow < NN;
            int gsafe = p ? grow : 0;
            const __half* gp = base + (size_t)gsafe * 128 + kb + cc8[l] * 8;
            cp16(&As[buf][SWZ(rr[l], cc8[l] * 4)], gp, p);
        }
        cp_commit();
    };

    uint4 breg[4];
    auto loadB = [&](int c) {
#pragma unroll
        for (int l = 0; l < 4; l++)
            breg[l] = wcat4[(size_t)rr[l] * 32 + c * 8 + cc8[l]];
    };

    issueA(0, 0);
    loadB(0);

#pragma unroll 1
    for (int c = 0; c < 4; c++) {
        cp_wait0();
        __syncthreads();          // As[c&1] visible; prev mma done

#pragma unroll
        for (int l = 0; l < 4; l++)
            *reinterpret_cast<uint4*>(&Bs[SWZ(rr[l], cc8[l] * 4)]) = breg[l];
        if (c < 3) {
            issueA(c + 1, (c + 1) & 1);   // overlaps with mma below
            loadB(c + 1);
        }

        __syncthreads();          // Bs visible

        const unsigned* Ab = As[c & 1];
#pragma unroll
        for (int ks = 0; ks < 4; ks++) {
            const int w0 = ks * 8;        // word base (k0 = ks*16 halves)

            unsigned a[4][4];
#pragma unroll
            for (int mi = 0; mi < 4; mi++) {
                int r = wm + mi * 16 + gr;
                a[mi][0] = Ab[SWZ(r,     w0 + gc)];
                a[mi][1] = Ab[SWZ(r + 8, w0 + gc)];
                a[mi][2] = Ab[SWZ(r,     w0 + gc + 4)];
                a[mi][3] = Ab[SWZ(r + 8, w0 + gc + 4)];
            }

            unsigned b[4][2];
#pragma unroll
            for (int ni = 0; ni < 4; ni++) {
                int n = wn + ni * 8 + gr;
                b[ni][0] = Bs[SWZ(n, w0 + gc)];
                b[ni][1] = Bs[SWZ(n, w0 + gc + 4)];
            }

#pragma unroll
            for (int mi = 0; mi < 4; mi++)
#pragma unroll
                for (int ni = 0; ni < 4; ni++)
                    mma_fp16(acc[mi][ni], a[mi], b[ni]);
        }
    }

    // --- epilogue: +bias, optional relu; fp16 or fp32 stores
#pragma unroll
    for (int ni = 0; ni < 4; ni++) {
        int col = wn + ni * 8 + gc * 2;
        float b0 = bias[col];
        float b1 = bias[col + 1];
#pragma unroll
        for (int mi = 0; mi < 4; mi++) {
            int r0 = bm0 + wm + mi * 16 + gr;
            float2 v0, v1;
            v0.x = acc[mi][ni][0] + b0;
            v0.y = acc[mi][ni][1] + b1;
            v1.x = acc[mi][ni][2] + b0;
            v1.y = acc[mi][ni][3] + b1;
            if (RELU) {
                v0.x = fmaxf(v0.x, 0.f); v0.y = fmaxf(v0.y, 0.f);
                v1.x = fmaxf(v1.x, 0.f); v1.y = fmaxf(v1.y, 0.f);
            }
            if (r0 < NN) {
                if (OUT_HALF)
                    *reinterpret_cast<__half2*>(&outh[(size_t)r0 * 128 + col]) =
                        __floats2half2_rn(v0.x, v0.y);
                else
                    *reinterpret_cast<float2*>(&out[(size_t)r0 * 128 + col]) = v0;
            }
            if (r0 + 8 < NN) {
                if (OUT_HALF)
                    *reinterpret_cast<__half2*>(&outh[(size_t)(r0 + 8) * 128 + col]) =
                        __floats2half2_rn(v1.x, v1.y);
                else
                    *reinterpret_cast<float2*>(&out[(size_t)(r0 + 8) * 128 + col]) = v1;
            }
        }
    }
}

// ---------------------------------------------------------------------------
// launch  (gemm1 is kernel launch #6 -> ncu capture slot)
// ---------------------------------------------------------------------------
extern "C" void kernel_launch(void* const* d_in, const int* in_sizes, int n_in,
                              void* d_out, int out_size) {
    const float* in_feat = (const float*)d_in[0];
    const float* weights = (const float*)d_in[1];
    const int*   src     = (const int*)d_in[2];
    const int*   dst     = (const int*)d_in[3];
    const float* Ws1     = (const float*)d_in[4];
    const float* b1      = (const float*)d_in[5];
    const float* Wn1     = (const float*)d_in[6];
    const float* Ws2     = (const float*)d_in[7];
    const float* b2      = (const float*)d_in[8];
    const float* Wn2     = (const float*)d_in[9];
    float* out = (float*)d_out;

    void *p_xh, *p_hh, *p_sh, *p_w;
    cudaGetSymbolAddress(&p_xh, g_xh);
    cudaGetSymbolAddress(&p_hh, g_hh);
    cudaGetSymbolAddress(&p_sh, g_sh);
    cudaGetSymbolAddress(&p_w, g_wcat);
    __half* xh = (__half*)p_xh;
    __half* hh = (__half*)p_hh;
    __half* sh = (__half*)p_sh;
    __half* w0 = (__half*)p_w;
    __half* w1 = w0 + 128 * 256;

    const int eb = (EE + 255) / 256;
    const int prep_blocks = (NN * 32 + 255) / 256;    // 12500
    const int gather_blocks = (NN * 32 + 255) / 256;  // 1 warp per node
    const int gemm_blocks = (NN + 127) / 128;

    k_prep<<<prep_blocks, 256>>>(in_feat, Ws1, Wn1, Ws2, Wn2);  // 1
    k_hist<<<eb, 256>>>(dst);                                   // 2
    k_scan<<<SCAN_BLOCKS, 256>>>();                             // 3
    k_fill<<<eb, 256>>>(src, dst, weights);                     // 4

    // Layer 1
    k_gather<<<gather_blocks, 256>>>(xh, sh);                   // 5
    k_gemm_fp16<true, true><<<gemm_blocks, 256>>>(              // 6 (profiled)
        xh, sh, w0, b1, nullptr, hh);

    // Layer 2
    k_gather<<<gather_blocks, 256>>>(hh, sh);                   // 7
    k_gemm_fp16<false, false><<<gemm_blocks, 256>>>(            // 8
        hh, sh, w1, b2, out, nullptr);
}